// round 3
// baseline (speedup 1.0000x reference)
#include <cuda_runtime.h>
#include <cstdint>
#include <cstddef>

#define FULLMASK 0xffffffffu

constexpr int Bb  = 16;
constexpr int Nn  = 256;
constexpr int Hh  = 1024;
constexpr int HIDh= 300;
constexpr int Ll  = 64;
constexpr int Mm  = Bb * Nn;        // 4096
constexpr int KP  = 304;            // padded 301 -> 304 (float4-friendly)

// ---------------- scratch (__device__ globals; no runtime allocation) ----------
__device__ float g_d1  [Mm * KP];                         // [4096][304]
__device__ float g_h1  [Mm * KP];                         // [4096][304]
__device__ float g_U   [Mm * Ll * KP];                    // [m][l][j] 318MB
__device__ float g_emis[Mm * Nn * Ll];                    // log_softmax(s) 268MB
__device__ float g_hist[Mm * Nn * Ll];                    // viterbi scores per step 268MB
__device__ float g_expT[Ll * Ll];
__device__ int   g_len [Bb];
__device__ float g_num [Mm];
__device__ float g_den [Mm];

// ---------------- K0: mask-format probe, lengths, exp(trans) -------------------
__global__ void k_pre(const void* __restrict__ maskp, const float* __restrict__ trans) {
    int tid = threadIdx.x;
    __shared__ int fmt_s;
    if (tid == 0) {
        // mask[0][0..] is guaranteed true (lengths >= N/2 >= 128)
        unsigned int w = *(const unsigned int*)maskp;
        int f = 0;                       // default: uint8 (0x01010101 probe)
        if (w == 1u)           f = 1;    // int32
        else if (w == 0x3f800000u) f = 2;// float32
        fmt_s = f;
    }
    __syncthreads();
    int fmt = fmt_s;
    if (tid < Bb) {
        int cnt = 0;
        for (int t = 0; t < Nn; t++) {
            bool v;
            if (fmt == 1)      v = ((const int*)maskp)[tid * Nn + t] != 0;
            else if (fmt == 2) v = ((const float*)maskp)[tid * Nn + t] != 0.f;
            else               v = ((const unsigned char*)maskp)[tid * Nn + t] != 0;
            cnt += v ? 1 : 0;
        }
        g_len[tid] = cnt;
    }
    for (int i = tid; i < Ll * Ll; i += blockDim.x) g_expT[i] = expf(trans[i]);
}

// ---------------- K1: MLP heads: relu(X @ W.T + b), concat ones, zero-pad ------
// blockIdx.z: 0 -> h (g_h1), 1 -> d (g_d1). Tile 64x64, K=1024, 256 threads, 4x4 micro.
__global__ void __launch_bounds__(256) k_mlp(const float* __restrict__ X,
                                             const float* __restrict__ Wh,
                                             const float* __restrict__ bh,
                                             const float* __restrict__ Wd,
                                             const float* __restrict__ bd) {
    const float* W    = blockIdx.z ? Wd : Wh;
    const float* bias = blockIdx.z ? bd : bh;
    float*       OUT  = blockIdx.z ? g_d1 : g_h1;
    const int m0 = blockIdx.x * 64, c0 = blockIdx.y * 64;
    __shared__ float As[16][64];
    __shared__ float Bs[16][64];
    const int tid = threadIdx.x;
    const int tm = tid >> 4, tn = tid & 15;
    const int lm = tid >> 2, lk = (tid & 3) * 4;
    float acc[4][4] = {};
    for (int k0 = 0; k0 < Hh; k0 += 16) {
        float4 a = *(const float4*)&X[(m0 + lm) * Hh + k0 + lk];
        As[lk + 0][lm] = a.x; As[lk + 1][lm] = a.y; As[lk + 2][lm] = a.z; As[lk + 3][lm] = a.w;
        float4 bv = make_float4(0.f, 0.f, 0.f, 0.f);
        if (c0 + lm < HIDh) bv = *(const float4*)&W[(c0 + lm) * Hh + k0 + lk];
        Bs[lk + 0][lm] = bv.x; Bs[lk + 1][lm] = bv.y; Bs[lk + 2][lm] = bv.z; Bs[lk + 3][lm] = bv.w;
        __syncthreads();
#pragma unroll
        for (int kk = 0; kk < 16; kk++) {
            float4 av = *(const float4*)&As[kk][tm * 4];
            float4 bb = *(const float4*)&Bs[kk][tn * 4];
            float ar[4] = {av.x, av.y, av.z, av.w};
            float br[4] = {bb.x, bb.y, bb.z, bb.w};
#pragma unroll
            for (int i = 0; i < 4; i++)
#pragma unroll
                for (int j = 0; j < 4; j++) acc[i][j] = fmaf(ar[i], br[j], acc[i][j]);
        }
        __syncthreads();
    }
#pragma unroll
    for (int i = 0; i < 4; i++) {
        int m = m0 + tm * 4 + i;
#pragma unroll
        for (int j = 0; j < 4; j++) {
            int c = c0 + tn * 4 + j;
            if (c < KP) {
                float v;
                if (c < HIDh)      v = fmaxf(acc[i][j] + bias[c], 0.f);
                else if (c == HIDh) v = 1.f;   // bias-augmentation "ones" column
                else                v = 0.f;   // zero pad 301..303
                OUT[m * KP + c] = v;
            }
        }
    }
}

// ---------------- K2: U[m][l][j] = sum_i d1[m][i] * W[l][i][j] ------------------
// grid: (m-tiles=64, j-tiles=5, l=64). Tile 64x64, K=304 (zero-padded A makes
// out-of-range W columns harmless; B loads are explicitly guarded).
__global__ void __launch_bounds__(256) k_gemmU(const float* __restrict__ W) {
    const int l  = blockIdx.z;
    const int m0 = blockIdx.x * 64, j0 = blockIdx.y * 64;
    __shared__ float As[16][64];
    __shared__ float Bs[16][64];
    const int tid = threadIdx.x;
    const int tm = tid >> 4, tn = tid & 15;
    const int lm = tid >> 2, lk = (tid & 3) * 4;
    const int bj = tid & 63, bk = tid >> 6;
    float acc[4][4] = {};
    const float* Wbase = W + (size_t)l * 90601;   // l * 301 * 301
    for (int i0 = 0; i0 < KP; i0 += 16) {
        float4 a = *(const float4*)&g_d1[(m0 + lm) * KP + i0 + lk];
        As[lk + 0][lm] = a.x; As[lk + 1][lm] = a.y; As[lk + 2][lm] = a.z; As[lk + 3][lm] = a.w;
#pragma unroll
        for (int r = 0; r < 4; r++) {
            int ii = i0 + bk + r * 4;
            float v = 0.f;
            if (ii < 301 && (j0 + bj) < 301) v = Wbase[ii * 301 + j0 + bj];
            Bs[bk + r * 4][bj] = v;
        }
        __syncthreads();
#pragma unroll
        for (int kk = 0; kk < 16; kk++) {
            float4 av = *(const float4*)&As[kk][tm * 4];
            float4 bb = *(const float4*)&Bs[kk][tn * 4];
            float ar[4] = {av.x, av.y, av.z, av.w};
            float br[4] = {bb.x, bb.y, bb.z, bb.w};
#pragma unroll
            for (int i = 0; i < 4; i++)
#pragma unroll
                for (int j = 0; j < 4; j++) acc[i][j] = fmaf(ar[i], br[j], acc[i][j]);
        }
        __syncthreads();
    }
#pragma unroll
    for (int i = 0; i < 4; i++) {
        int m = m0 + tm * 4 + i;
        float* urow = &g_U[((size_t)m * Ll + l) * KP];
#pragma unroll
        for (int j = 0; j < 4; j++) {
            int jj = j0 + tn * 4 + j;
            if (jj < KP) urow[jj] = (jj < 301) ? acc[i][j] : 0.f;  // pad j 301..303 = 0
        }
    }
}

// ---------------- K3: s[b,x,y,l] = sum_j U[b,x,l,j] * h1[b,y,j] -----------------
// Per batch: A = U rows [b*16384 .. +16384) as [16384][304]; B = h1[b] [256][304].
// One 64-row tile = one x with all 64 l. Store directly into d_out s_flat layout.
// NOTE: sout base is d_out+1 -> only 4-byte aligned. Scalar stores ONLY.
__global__ void __launch_bounds__(256) k_gemmS(float* __restrict__ sout) {
    const int b  = blockIdx.z;
    const int r0 = blockIdx.x * 64;       // r = x*64 + l -> tile spans one x
    const int y0 = blockIdx.y * 64;
    const int x  = blockIdx.x;            // r0/64
    __shared__ float As[16][64];
    __shared__ float Bs[16][64];
    const int tid = threadIdx.x;
    const int tm = tid >> 4, tn = tid & 15;
    const int lm = tid >> 2, lk = (tid & 3) * 4;
    float acc[4][4] = {};
    const size_t Abase = ((size_t)b * 16384 + r0) * KP;
    const size_t Bbase = ((size_t)b * 256 + y0) * KP;
    for (int jj0 = 0; jj0 < KP; jj0 += 16) {
        float4 a = *(const float4*)&g_U[Abase + (size_t)lm * KP + jj0 + lk];
        As[lk + 0][lm] = a.x; As[lk + 1][lm] = a.y; As[lk + 2][lm] = a.z; As[lk + 3][lm] = a.w;
        float4 bv = *(const float4*)&g_h1[Bbase + (size_t)lm * KP + jj0 + lk];
        Bs[lk + 0][lm] = bv.x; Bs[lk + 1][lm] = bv.y; Bs[lk + 2][lm] = bv.z; Bs[lk + 3][lm] = bv.w;
        __syncthreads();
#pragma unroll
        for (int kk = 0; kk < 16; kk++) {
            float4 av = *(const float4*)&As[kk][tm * 4];
            float4 bb = *(const float4*)&Bs[kk][tn * 4];
            float ar[4] = {av.x, av.y, av.z, av.w};
            float br[4] = {bb.x, bb.y, bb.z, bb.w};
#pragma unroll
            for (int i = 0; i < 4; i++)
#pragma unroll
                for (int j = 0; j < 4; j++) acc[i][j] = fmaf(ar[i], br[j], acc[i][j]);
        }
        __syncthreads();
    }
    const int mrow = b * 256 + x;
#pragma unroll
    for (int j = 0; j < 4; j++) {
        int y = y0 + tn * 4 + j;
        size_t o = ((size_t)mrow * 256 + y) * 64 + tm * 4;   // l = tm*4..+3
        sout[o + 0] = acc[0][j];
        sout[o + 1] = acc[1][j];
        sout[o + 2] = acc[2][j];
        sout[o + 3] = acc[3][j];
    }
}

// ---------------- K4: emissions = log_softmax(s, axis=-1) -----------------------
__global__ void __launch_bounds__(128) k_lse(const float* __restrict__ s) {
    int w    = (blockIdx.x << 2) + (threadIdx.x >> 5);   // (m,y) row index
    int lane = threadIdx.x & 31;
    size_t base = (size_t)w * 64;
    float s1 = s[base + lane], s2 = s[base + lane + 32];
    float mx = fmaxf(s1, s2);
#pragma unroll
    for (int o = 16; o; o >>= 1) mx = fmaxf(mx, __shfl_xor_sync(FULLMASK, mx, o));
    float e = expf(s1 - mx) + expf(s2 - mx);
#pragma unroll
    for (int o = 16; o; o >>= 1) e += __shfl_xor_sync(FULLMASK, e, o);
    float lse = mx + logf(e);
    g_emis[base + lane]      = s1 - lse;
    g_emis[base + lane + 32] = s2 - lse;
}

// ---------------- K5: CRF numerator per row -------------------------------------
__global__ void __launch_bounds__(256) k_num(const int* __restrict__ labels,
                                             const float* __restrict__ trans,
                                             const float* __restrict__ startT,
                                             const float* __restrict__ endT) {
    int m    = blockIdx.x * 8 + (threadIdx.x >> 5);
    int lane = threadIdx.x & 31;
    int len  = g_len[m >> 8];
    const int*   tg = labels + m * Nn;
    const float* em = g_emis + (size_t)m * Nn * Ll;
    float part = 0.f;
    for (int t = lane; t < len; t += 32) {
        int tt = tg[t];
        part += em[t * 64 + tt];
        if (t >= 1) part += trans[tg[t - 1] * 64 + tt];
    }
#pragma unroll
    for (int o = 16; o; o >>= 1) part += __shfl_xor_sync(FULLMASK, part, o);
    if (lane == 0) g_num[m] = part + startT[tg[0]] + endT[tg[len - 1]];
}

// ---------------- K6: fused forward (logsumexp via exp-matvec) + Viterbi scan ---
// One warp per row; lane owns states (lane, lane+32). Stores viterbi score
// vectors for every step into g_hist (argmax recovered at backtrace).
__global__ void __launch_bounds__(256) k_scan(const float* __restrict__ trans,
                                              const float* __restrict__ startT,
                                              const float* __restrict__ endT) {
    __shared__ float sT[64 * 64];
    __shared__ float sE[64 * 64];
    __shared__ float sS[64], sEn[64];
    int tid = threadIdx.x;
    for (int i = tid; i < 4096; i += 256) { sT[i] = trans[i]; sE[i] = g_expT[i]; }
    if (tid < 64) { sS[tid] = startT[tid]; sEn[tid] = endT[tid]; }
    __syncthreads();
    int m = blockIdx.x * 8 + (tid >> 5);
    int lane = tid & 31, k1 = lane, k2 = lane + 32;
    int len = g_len[m >> 8];
    const float* em   = g_emis + (size_t)m * Nn * Ll;
    float*       hist = g_hist + (size_t)m * Nn * Ll;
    float e1 = em[k1], e2 = em[k2];
    float a1 = sS[k1] + e1, a2 = sS[k2] + e2;
    float v1 = a1, v2 = a2;
    hist[k1] = v1; hist[k2] = v2;
    for (int t = 1; t < len; t++) {
        float et1 = em[t * 64 + k1], et2 = em[t * 64 + k2];
        // forward: shift by max(alpha)
        float mx = fmaxf(a1, a2);
#pragma unroll
        for (int o = 16; o; o >>= 1) mx = fmaxf(mx, __shfl_xor_sync(FULLMASK, mx, o));
        float p1 = __expf(a1 - mx), p2 = __expf(a2 - mx);
        float q1 = 0.f, q2 = 0.f, b1 = -1e30f, b2 = -1e30f;
#pragma unroll
        for (int j = 0; j < 32; j++) {
            float vj = __shfl_sync(FULLMASK, v1, j);
            float pj = __shfl_sync(FULLMASK, p1, j);
            b1 = fmaxf(b1, vj + sT[j * 64 + k1]);
            b2 = fmaxf(b2, vj + sT[j * 64 + k2]);
            q1 = fmaf(pj, sE[j * 64 + k1], q1);
            q2 = fmaf(pj, sE[j * 64 + k2], q2);
        }
#pragma unroll
        for (int j = 0; j < 32; j++) {
            float vj = __shfl_sync(FULLMASK, v2, j);
            float pj = __shfl_sync(FULLMASK, p2, j);
            b1 = fmaxf(b1, vj + sT[(j + 32) * 64 + k1]);
            b2 = fmaxf(b2, vj + sT[(j + 32) * 64 + k2]);
            q1 = fmaf(pj, sE[(j + 32) * 64 + k1], q1);
            q2 = fmaf(pj, sE[(j + 32) * 64 + k2], q2);
        }
        v1 = b1 + et1; v2 = b2 + et2;
        a1 = mx + __logf(q1) + et1;
        a2 = mx + __logf(q2) + et2;
        hist[t * 64 + k1] = v1; hist[t * 64 + k2] = v2;
    }
    // den = logsumexp(alpha + end_trans)
    float z1 = a1 + sEn[k1], z2 = a2 + sEn[k2];
    float mx = fmaxf(z1, z2);
#pragma unroll
    for (int o = 16; o; o >>= 1) mx = fmaxf(mx, __shfl_xor_sync(FULLMASK, mx, o));
    float e = __expf(z1 - mx) + __expf(z2 - mx);
#pragma unroll
    for (int o = 16; o; o >>= 1) e += __shfl_xor_sync(FULLMASK, e, o);
    if (lane == 0) g_den[m] = mx + __logf(e);
}

// ---------------- K7: Viterbi backtrace (argmax recovered from stored scores) ---
__global__ void __launch_bounds__(256) k_bt(const float* __restrict__ trans,
                                            const float* __restrict__ endT,
                                            float* __restrict__ dec_out) {
    __shared__ float sT[64 * 65];     // padded: column reads must be conflict-free
    __shared__ float sEn[64];
    int tid = threadIdx.x;
    for (int i = tid; i < 4096; i += 256) { int j = i >> 6, k = i & 63; sT[j * 65 + k] = trans[i]; }
    if (tid < 64) sEn[tid] = endT[tid];
    __syncthreads();
    int m = blockIdx.x * 8 + (tid >> 5), lane = tid & 31, k1 = lane, k2 = lane + 32;
    int len = g_len[m >> 8];
    const float* hist = g_hist + (size_t)m * Nn * Ll;
    float* dec = dec_out + (size_t)m * Nn;
    // last = argmax(score_final + end_trans), first-index tie-break like jnp.argmax
    float f1 = hist[(len - 1) * 64 + k1] + sEn[k1];
    float f2 = hist[(len - 1) * 64 + k2] + sEn[k2];
    float bv; int bi;
    if (f2 > f1) { bv = f2; bi = k2; } else { bv = f1; bi = k1; }
#pragma unroll
    for (int o = 16; o; o >>= 1) {
        float ov = __shfl_xor_sync(FULLMASK, bv, o);
        int   oi = __shfl_xor_sync(FULLMASK, bi, o);
        if (ov > bv || (ov == bv && oi < bi)) { bv = ov; bi = oi; }
    }
    int cur = bi;
    for (int j = len - 1 + lane; j < Nn; j += 32) dec[j] = (float)cur;  // frozen tail
    for (int t = len - 1; t >= 1; t--) {
        float h1v = hist[(t - 1) * 64 + k1] + sT[k1 * 65 + cur];
        float h2v = hist[(t - 1) * 64 + k2] + sT[k2 * 65 + cur];
        float bv2; int bi2;
        if (h2v > h1v) { bv2 = h2v; bi2 = k2; } else { bv2 = h1v; bi2 = k1; }
#pragma unroll
        for (int o = 16; o; o >>= 1) {
            float ov = __shfl_xor_sync(FULLMASK, bv2, o);
            int   oi = __shfl_xor_sync(FULLMASK, bi2, o);
            if (ov > bv2 || (ov == bv2 && oi < bi2)) { bv2 = ov; bi2 = oi; }
        }
        cur = bi2;
        if (lane == 0) dec[t - 1] = (float)cur;
    }
}

// ---------------- K8: deterministic loss reduction ------------------------------
__global__ void k_loss(float* __restrict__ out) {
    __shared__ float sm[256];
    int tid = threadIdx.x;
    float s = 0.f;
    for (int i = 0; i < 16; i++) {
        int m = tid * 16 + i;
        bool w = (m & 255) < g_len[m >> 8];   // row weight = mask at row's own position
        if (w) s += g_num[m] - g_den[m];
    }
    sm[tid] = s;
    __syncthreads();
    for (int st = 128; st; st >>= 1) { if (tid < st) sm[tid] += sm[tid + st]; __syncthreads(); }
    if (tid == 0) out[0] = -sm[0];
}

// ---------------- launch --------------------------------------------------------
extern "C" void kernel_launch(void* const* d_in, const int* in_sizes, int n_in,
                              void* d_out, int out_size) {
    (void)in_sizes; (void)n_in; (void)out_size;
    const float* input  = (const float*)d_in[0];
    const void*  mask   = d_in[1];
    const int*   labels = (const int*)d_in[2];
    const float* Wh     = (const float*)d_in[3];
    const float* bh     = (const float*)d_in[4];
    const float* Wd     = (const float*)d_in[5];
    const float* bd     = (const float*)d_in[6];
    const float* Wb     = (const float*)d_in[7];
    const float* startT = (const float*)d_in[8];
    const float* trans  = (const float*)d_in[9];
    const float* endT   = (const float*)d_in[10];

    float* out     = (float*)d_out;
    float* s_out   = out + 1;                                  // s_flat [4096,256,64]
    float* dec_out = out + 1 + (size_t)Mm * Nn * Ll;           // decoded [4096,256]

    k_pre  <<<1, 256>>>(mask, trans);
    k_mlp  <<<dim3(64, 5, 2),  256>>>(input, Wh, bh, Wd, bd);
    k_gemmU<<<dim3(64, 5, 64), 256>>>(Wb);
    k_gemmS<<<dim3(256, 4, 16),256>>>(s_out);
    k_lse  <<<262144, 128>>>(s_out);
    k_num  <<<512, 256>>>(labels, trans, startT, endT);
    k_scan <<<512, 256>>>(trans, startT, endT);
    k_bt   <<<512, 256>>>(trans, endT, dec_out);
    k_loss <<<1, 256>>>(out);
}

// round 4
// speedup vs baseline: 1.0795x; 1.0795x over previous
#include <cuda_runtime.h>
#include <cstdint>
#include <cstddef>

#define FULLMASK 0xffffffffu

constexpr int Bb  = 16;
constexpr int Nn  = 256;
constexpr int Hh  = 1024;
constexpr int HIDh= 300;
constexpr int Ll  = 64;
constexpr int Mm  = Bb * Nn;        // 4096
constexpr int KP  = 304;            // padded 301 -> 304
constexpr int NU  = Ll * KP;        // 19456 merged (l,j) columns of U

// ---------------- scratch ----------------
__device__ float g_d1  [Mm * KP];
__device__ float g_h1  [Mm * KP];
__device__ float g_U   [(size_t)Mm * NU];                 // [m][l*304+j]
__device__ float g_emis[(size_t)Mm * Nn * Ll];
__device__ float g_hist[(size_t)Mm * Nn * Ll];
__device__ float g_expT[Ll * Ll];
__device__ int   g_len [Bb];
__device__ float g_num [Mm];
__device__ float g_den [Mm];

// packed-fp32 helpers (sm_100+ FFMA2 path; ptxas never auto-fuses)
#define FMA2(acc, a, b) asm("fma.rn.f32x2 %0, %1, %2, %0;" : "+l"(acc) : "l"(a), "l"(b))
#define DUP2(d, f)      asm("mov.b64 %0, {%1, %1};" : "=l"(d) : "r"(__float_as_uint(f)))
#define UNPK2(lo, hi, s) do { unsigned _ulo, _uhi; \
    asm("mov.b64 {%0, %1}, %2;" : "=r"(_ulo), "=r"(_uhi) : "l"(s)); \
    lo = __uint_as_float(_ulo); hi = __uint_as_float(_uhi); } while(0)

// ---------------- K0: mask probe, lengths, exp(trans) ----------------
__global__ void k_pre(const void* __restrict__ maskp, const float* __restrict__ trans) {
    int tid = threadIdx.x;
    __shared__ int fmt_s;
    if (tid == 0) {
        unsigned int w = *(const unsigned int*)maskp;
        int f = 0;
        if (w == 1u)               f = 1;   // int32
        else if (w == 0x3f800000u) f = 2;   // float32
        fmt_s = f;
    }
    __syncthreads();
    int fmt = fmt_s;
    if (tid < Bb) {
        int cnt = 0;
        for (int t = 0; t < Nn; t++) {
            bool v;
            if (fmt == 1)      v = ((const int*)maskp)[tid * Nn + t] != 0;
            else if (fmt == 2) v = ((const float*)maskp)[tid * Nn + t] != 0.f;
            else               v = ((const unsigned char*)maskp)[tid * Nn + t] != 0;
            cnt += v ? 1 : 0;
        }
        g_len[tid] = cnt;
    }
    for (int i = tid; i < Ll * Ll; i += blockDim.x) g_expT[i] = expf(trans[i]);
}

// ======================================================================
// 128x128-tile, 8x8-per-thread, FFMA2 GEMM family. 256 threads.
// Thread map: tn = tid & 15 (8 n-cols), tm = tid >> 4 (8 m-rows).
// acc[p][q]: p = m-pair (rows 2p, 2p+1), q = n col.
// ======================================================================

#define GEMM_DECLS                                                         \
    __shared__ float As[16][128];                                          \
    __shared__ float Bs[16][128];                                          \
    const int tid = threadIdx.x;                                           \
    const int tn = tid & 15, tm = tid >> 4;                                \
    const int a_r = tid >> 1, a_c = (tid & 1) * 8;                         \
    unsigned long long acc[4][8];                                          \
    _Pragma("unroll") for (int p = 0; p < 4; p++)                          \
    _Pragma("unroll") for (int q = 0; q < 8; q++) acc[p][q] = 0ull;

#define GEMM_COMPUTE16                                                     \
    _Pragma("unroll")                                                      \
    for (int kk = 0; kk < 16; kk++) {                                      \
        ulonglong2 a01 = *(const ulonglong2*)&As[kk][tm * 8];              \
        ulonglong2 a23 = *(const ulonglong2*)&As[kk][tm * 8 + 4];          \
        float4 b0 = *(const float4*)&Bs[kk][tn * 8];                       \
        float4 b1 = *(const float4*)&Bs[kk][tn * 8 + 4];                   \
        float bq[8] = {b0.x, b0.y, b0.z, b0.w, b1.x, b1.y, b1.z, b1.w};    \
        _Pragma("unroll")                                                  \
        for (int q = 0; q < 8; q++) {                                      \
            unsigned long long bd; DUP2(bd, bq[q]);                        \
            FMA2(acc[0][q], a01.x, bd);                                    \
            FMA2(acc[1][q], a01.y, bd);                                    \
            FMA2(acc[2][q], a23.x, bd);                                    \
            FMA2(acc[3][q], a23.y, bd);                                    \
        }                                                                  \
    }

// ---------------- K1: fused MLP heads GEMM --------------------------------
// C[m][n], n<304 -> h-head col n ; 304<=n<608 -> d-head col n-304 ; n>=608 pad.
// M=4096, N=640(608), K=1024. B[k][n] = W[c][k].
__global__ void __launch_bounds__(256, 2) k_mlp(const float* __restrict__ X,
                                                const float* __restrict__ Wh,
                                                const float* __restrict__ bh,
                                                const float* __restrict__ Wd,
                                                const float* __restrict__ bd) {
    const int n0 = blockIdx.x * 128, m0 = blockIdx.y * 128;
    GEMM_DECLS
    const int nB   = n0 + a_r;
    const int head = nB >= 304;
    const int c    = head ? nB - 304 : nB;
    const float* Wsrc = head ? Wd : Wh;
    const bool bvalid = (nB < 608) && (c < HIDh);

    float4 rA0, rA1, rB0, rB1;
    {   // prefetch chunk 0
        const float* ap = &X[(m0 + a_r) * Hh + a_c];
        rA0 = *(const float4*)ap; rA1 = *(const float4*)(ap + 4);
        rB0 = rB1 = make_float4(0.f, 0.f, 0.f, 0.f);
        if (bvalid) { const float* bp = &Wsrc[c * Hh + a_c];
                      rB0 = *(const float4*)bp; rB1 = *(const float4*)(bp + 4); }
    }
    for (int k0 = 0; k0 < Hh; k0 += 16) {
        As[a_c + 0][a_r] = rA0.x; As[a_c + 1][a_r] = rA0.y;
        As[a_c + 2][a_r] = rA0.z; As[a_c + 3][a_r] = rA0.w;
        As[a_c + 4][a_r] = rA1.x; As[a_c + 5][a_r] = rA1.y;
        As[a_c + 6][a_r] = rA1.z; As[a_c + 7][a_r] = rA1.w;
        Bs[a_c + 0][a_r] = rB0.x; Bs[a_c + 1][a_r] = rB0.y;
        Bs[a_c + 2][a_r] = rB0.z; Bs[a_c + 3][a_r] = rB0.w;
        Bs[a_c + 4][a_r] = rB1.x; Bs[a_c + 5][a_r] = rB1.y;
        Bs[a_c + 6][a_r] = rB1.z; Bs[a_c + 7][a_r] = rB1.w;
        __syncthreads();
        if (k0 + 16 < Hh) {
            const float* ap = &X[(m0 + a_r) * Hh + k0 + 16 + a_c];
            rA0 = *(const float4*)ap; rA1 = *(const float4*)(ap + 4);
            if (bvalid) { const float* bp = &Wsrc[c * Hh + k0 + 16 + a_c];
                          rB0 = *(const float4*)bp; rB1 = *(const float4*)(bp + 4); }
        }
        GEMM_COMPUTE16
        __syncthreads();
    }
#pragma unroll
    for (int p = 0; p < 4; p++)
#pragma unroll
    for (int q = 0; q < 8; q++) {
        float lo, hi; UNPK2(lo, hi, acc[p][q]);
        int n = n0 + tn * 8 + q;
        if (n >= 608) continue;
        int hd = n >= 304; int cc = hd ? n - 304 : n;
        float* dst = hd ? g_d1 : g_h1;
        const float* bias = hd ? bd : bh;
        float v0, v1;
        if (cc < HIDh)      { float bv = bias[cc]; v0 = fmaxf(lo + bv, 0.f); v1 = fmaxf(hi + bv, 0.f); }
        else if (cc == HIDh){ v0 = v1 = 1.f; }
        else                { v0 = v1 = 0.f; }
        int m = m0 + tm * 8 + 2 * p;
        dst[m * KP + cc]       = v0;
        dst[(m + 1) * KP + cc] = v1;
    }
}

// ---------------- K2: U = d1 @ W'  (M=4096, N=19456, K=304) ----------------
// B[k=i][col] = (j<301 && i<301) ? W[l*90601 + i*301 + j] : 0, col = l*304+j.
__global__ void __launch_bounds__(256, 2) k_gemmU(const float* __restrict__ W) {
    const int n0 = blockIdx.x * 128, m0 = blockIdx.y * 128;
    GEMM_DECLS
    const int b_k = tid >> 4, b_n = (tid & 15) * 8;

    float4 rA0, rA1; float rB[8];
    {
        const float* ap = &g_d1[(m0 + a_r) * KP + a_c];
        rA0 = *(const float4*)ap; rA1 = *(const float4*)(ap + 4);
        int i = b_k;
#pragma unroll
        for (int q = 0; q < 8; q++) {
            int col = n0 + b_n + q, l = col / KP, j = col - l * KP;
            rB[q] = (j < 301) ? W[(size_t)l * 90601 + i * 301 + j] : 0.f;
        }
    }
    for (int k0 = 0; k0 < KP; k0 += 16) {
        As[a_c + 0][a_r] = rA0.x; As[a_c + 1][a_r] = rA0.y;
        As[a_c + 2][a_r] = rA0.z; As[a_c + 3][a_r] = rA0.w;
        As[a_c + 4][a_r] = rA1.x; As[a_c + 5][a_r] = rA1.y;
        As[a_c + 6][a_r] = rA1.z; As[a_c + 7][a_r] = rA1.w;
#pragma unroll
        for (int q = 0; q < 8; q++) Bs[b_k][b_n + q] = rB[q];
        __syncthreads();
        if (k0 + 16 < KP) {
            const float* ap = &g_d1[(m0 + a_r) * KP + k0 + 16 + a_c];
            rA0 = *(const float4*)ap; rA1 = *(const float4*)(ap + 4);
            int i = k0 + 16 + b_k;
#pragma unroll
            for (int q = 0; q < 8; q++) {
                int col = n0 + b_n + q, l = col / KP, j = col - l * KP;
                rB[q] = (j < 301 && i < 301) ? W[(size_t)l * 90601 + i * 301 + j] : 0.f;
            }
        }
        GEMM_COMPUTE16
        __syncthreads();
    }
#pragma unroll
    for (int p = 0; p < 4; p++) {
        int m = m0 + tm * 8 + 2 * p;
        float* u0 = &g_U[(size_t)m * NU];
        float* u1 = &g_U[(size_t)(m + 1) * NU];
#pragma unroll
        for (int q = 0; q < 8; q++) {
            float lo, hi; UNPK2(lo, hi, acc[p][q]);
            int col = n0 + tn * 8 + q;
            int j = col % KP;
            bool ok = j < 301;
            u0[col] = ok ? lo : 0.f;
            u1[col] = ok ? hi : 0.f;
        }
    }
}

// ---------------- K3: S per batch (M=16384, N=256, K=304) -------------------
// A = g_U rows b*16384.., B = g_h1 rows b*256... Output scattered into s_flat.
__global__ void __launch_bounds__(256, 2) k_gemmS(float* __restrict__ sout) {
    const int b  = blockIdx.z;
    const int n0 = blockIdx.x * 128, m0 = blockIdx.y * 128;
    GEMM_DECLS
    const size_t Arow0 = (size_t)(b * 16384 + m0);
    const size_t Brow0 = (size_t)(b * 256 + n0);

    float4 rA0, rA1, rB0, rB1;
    {
        const float* ap = &g_U[(Arow0 + a_r) * KP + a_c];
        rA0 = *(const float4*)ap; rA1 = *(const float4*)(ap + 4);
        const float* bp = &g_h1[(Brow0 + a_r) * KP + a_c];
        rB0 = *(const float4*)bp; rB1 = *(const float4*)(bp + 4);
    }
    for (int k0 = 0; k0 < KP; k0 += 16) {
        As[a_c + 0][a_r] = rA0.x; As[a_c + 1][a_r] = rA0.y;
        As[a_c + 2][a_r] = rA0.z; As[a_c + 3][a_r] = rA0.w;
        As[a_c + 4][a_r] = rA1.x; As[a_c + 5][a_r] = rA1.y;
        As[a_c + 6][a_r] = rA1.z; As[a_c + 7][a_r] = rA1.w;
        Bs[a_c + 0][a_r] = rB0.x; Bs[a_c + 1][a_r] = rB0.y;
        Bs[a_c + 2][a_r] = rB0.z; Bs[a_c + 3][a_r] = rB0.w;
        Bs[a_c + 4][a_r] = rB1.x; Bs[a_c + 5][a_r] = rB1.y;
        Bs[a_c + 6][a_r] = rB1.z; Bs[a_c + 7][a_r] = rB1.w;
        __syncthreads();
        if (k0 + 16 < KP) {
            const float* ap = &g_U[(Arow0 + a_r) * KP + k0 + 16 + a_c];
            rA0 = *(const float4*)ap; rA1 = *(const float4*)(ap + 4);
            const float* bp = &g_h1[(Brow0 + a_r) * KP + k0 + 16 + a_c];
            rB0 = *(const float4*)bp; rB1 = *(const float4*)(bp + 4);
        }
        GEMM_COMPUTE16
        __syncthreads();
    }
    // rows r = m0 + tm*8 + 2p(+1): r = x*64 + l ; out[((b*256+x)*256+y)*64 + l]
#pragma unroll
    for (int p = 0; p < 4; p++) {
        int r  = m0 + tm * 8 + 2 * p;
        int x  = r >> 6, l = r & 63;
        size_t base = ((size_t)(b * 256 + x) * 256) * 64;
#pragma unroll
        for (int q = 0; q < 8; q++) {
            float lo, hi; UNPK2(lo, hi, acc[p][q]);
            int y = n0 + tn * 8 + q;
            sout[base + (size_t)y * 64 + l]     = lo;
            sout[base + (size_t)y * 64 + l + 1] = hi;
        }
    }
}

// ---------------- K4: emissions = log_softmax(s, -1) ----------------
__global__ void __launch_bounds__(128) k_lse(const float* __restrict__ s) {
    int w    = (blockIdx.x << 2) + (threadIdx.x >> 5);
    int lane = threadIdx.x & 31;
    size_t base = (size_t)w * 64;
    float s1 = s[base + lane], s2 = s[base + lane + 32];
    float mx = fmaxf(s1, s2);
#pragma unroll
    for (int o = 16; o; o >>= 1) mx = fmaxf(mx, __shfl_xor_sync(FULLMASK, mx, o));
    float e = expf(s1 - mx) + expf(s2 - mx);
#pragma unroll
    for (int o = 16; o; o >>= 1) e += __shfl_xor_sync(FULLMASK, e, o);
    float lse = mx + logf(e);
    g_emis[base + lane]      = s1 - lse;
    g_emis[base + lane + 32] = s2 - lse;
}

// ---------------- K5: CRF numerator ----------------
__global__ void __launch_bounds__(256) k_num(const int* __restrict__ labels,
                                             const float* __restrict__ trans,
                                             const float* __restrict__ startT,
                                             const float* __restrict__ endT) {
    int m    = blockIdx.x * 8 + (threadIdx.x >> 5);
    int lane = threadIdx.x & 31;
    int len  = g_len[m >> 8];
    const int*   tg = labels + m * Nn;
    const float* em = g_emis + (size_t)m * Nn * Ll;
    float part = 0.f;
    for (int t = lane; t < len; t += 32) {
        int tt = tg[t];
        part += em[t * 64 + tt];
        if (t >= 1) part += trans[tg[t - 1] * 64 + tt];
    }
#pragma unroll
    for (int o = 16; o; o >>= 1) part += __shfl_xor_sync(FULLMASK, part, o);
    if (lane == 0) g_num[m] = part + startT[tg[0]] + endT[tg[len - 1]];
}

// ---------------- K6: fused forward + Viterbi scan ----------------
__global__ void __launch_bounds__(256) k_scan(const float* __restrict__ trans,
                                              const float* __restrict__ startT,
                                              const float* __restrict__ endT) {
    __shared__ float sT[64 * 64];
    __shared__ float sE[64 * 64];
    __shared__ float sS[64], sEn[64];
    int tid = threadIdx.x;
    for (int i = tid; i < 4096; i += 256) { sT[i] = trans[i]; sE[i] = g_expT[i]; }
    if (tid < 64) { sS[tid] = startT[tid]; sEn[tid] = endT[tid]; }
    __syncthreads();
    int m = blockIdx.x * 8 + (tid >> 5);
    int lane = tid & 31, k1 = lane, k2 = lane + 32;
    int len = g_len[m >> 8];
    const float* em   = g_emis + (size_t)m * Nn * Ll;
    float*       hist = g_hist + (size_t)m * Nn * Ll;
    float e1 = em[k1], e2 = em[k2];
    float a1 = sS[k1] + e1, a2 = sS[k2] + e2;
    float v1 = a1, v2 = a2;
    hist[k1] = v1; hist[k2] = v2;
    for (int t = 1; t < len; t++) {
        float et1 = em[t * 64 + k1], et2 = em[t * 64 + k2];
        float mx = fmaxf(a1, a2);
#pragma unroll
        for (int o = 16; o; o >>= 1) mx = fmaxf(mx, __shfl_xor_sync(FULLMASK, mx, o));
        float p1 = __expf(a1 - mx), p2 = __expf(a2 - mx);
        float q1 = 0.f, q2 = 0.f, b1 = -1e30f, b2 = -1e30f;
#pragma unroll
        for (int j = 0; j < 32; j++) {
            float vj = __shfl_sync(FULLMASK, v1, j);
            float pj = __shfl_sync(FULLMASK, p1, j);
            b1 = fmaxf(b1, vj + sT[j * 64 + k1]);
            b2 = fmaxf(b2, vj + sT[j * 64 + k2]);
            q1 = fmaf(pj, sE[j * 64 + k1], q1);
            q2 = fmaf(pj, sE[j * 64 + k2], q2);
        }
#pragma unroll
        for (int j = 0; j < 32; j++) {
            float vj = __shfl_sync(FULLMASK, v2, j);
            float pj = __shfl_sync(FULLMASK, p2, j);
            b1 = fmaxf(b1, vj + sT[(j + 32) * 64 + k1]);
            b2 = fmaxf(b2, vj + sT[(j + 32) * 64 + k2]);
            q1 = fmaf(pj, sE[(j + 32) * 64 + k1], q1);
            q2 = fmaf(pj, sE[(j + 32) * 64 + k2], q2);
        }
        v1 = b1 + et1; v2 = b2 + et2;
        a1 = mx + __logf(q1) + et1;
        a2 = mx + __logf(q2) + et2;
        hist[t * 64 + k1] = v1; hist[t * 64 + k2] = v2;
    }
    float z1 = a1 + sEn[k1], z2 = a2 + sEn[k2];
    float mx = fmaxf(z1, z2);
#pragma unroll
    for (int o = 16; o; o >>= 1) mx = fmaxf(mx, __shfl_xor_sync(FULLMASK, mx, o));
    float e = __expf(z1 - mx) + __expf(z2 - mx);
#pragma unroll
    for (int o = 16; o; o >>= 1) e += __shfl_xor_sync(FULLMASK, e, o);
    if (lane == 0) g_den[m] = mx + __logf(e);
}

// ---------------- K7: Viterbi backtrace ----------------
__global__ void __launch_bounds__(256) k_bt(const float* __restrict__ trans,
                                            const float* __restrict__ endT,
                                            float* __restrict__ dec_out) {
    __shared__ float sT[64 * 65];
    __shared__ float sEn[64];
    int tid = threadIdx.x;
    for (int i = tid; i < 4096; i += 256) { int j = i >> 6, k = i & 63; sT[j * 65 + k] = trans[i]; }
    if (tid < 64) sEn[tid] = endT[tid];
    __syncthreads();
    int m = blockIdx.x * 8 + (tid >> 5), lane = tid & 31, k1 = lane, k2 = lane + 32;
    int len = g_len[m >> 8];
    const float* hist = g_hist + (size_t)m * Nn * Ll;
    float* dec = dec_out + (size_t)m * Nn;
    float f1 = hist[(len - 1) * 64 + k1] + sEn[k1];
    float f2 = hist[(len - 1) * 64 + k2] + sEn[k2];
    float bv; int bi;
    if (f2 > f1) { bv = f2; bi = k2; } else { bv = f1; bi = k1; }
#pragma unroll
    for (int o = 16; o; o >>= 1) {
        float ov = __shfl_xor_sync(FULLMASK, bv, o);
        int   oi = __shfl_xor_sync(FULLMASK, bi, o);
        if (ov > bv || (ov == bv && oi < bi)) { bv = ov; bi = oi; }
    }
    int cur = bi;
    for (int j = len - 1 + lane; j < Nn; j += 32) dec[j] = (float)cur;
    for (int t = len - 1; t >= 1; t--) {
        float h1v = hist[(t - 1) * 64 + k1] + sT[k1 * 65 + cur];
        float h2v = hist[(t - 1) * 64 + k2] + sT[k2 * 65 + cur];
        float bv2; int bi2;
        if (h2v > h1v) { bv2 = h2v; bi2 = k2; } else { bv2 = h1v; bi2 = k1; }
#pragma unroll
        for (int o = 16; o; o >>= 1) {
            float ov = __shfl_xor_sync(FULLMASK, bv2, o);
            int   oi = __shfl_xor_sync(FULLMASK, bi2, o);
            if (ov > bv2 || (ov == bv2 && oi < bi2)) { bv2 = ov; bi2 = oi; }
        }
        cur = bi2;
        if (lane == 0) dec[t - 1] = (float)cur;
    }
}

// ---------------- K8: loss reduction ----------------
__global__ void k_loss(float* __restrict__ out) {
    __shared__ float sm[256];
    int tid = threadIdx.x;
    float s = 0.f;
    for (int i = 0; i < 16; i++) {
        int m = tid * 16 + i;
        bool w = (m & 255) < g_len[m >> 8];
        if (w) s += g_num[m] - g_den[m];
    }
    sm[tid] = s;
    __syncthreads();
    for (int st = 128; st; st >>= 1) { if (tid < st) sm[tid] += sm[tid + st]; __syncthreads(); }
    if (tid == 0) out[0] = -sm[0];
}

// ---------------- launch ----------------
extern "C" void kernel_launch(void* const* d_in, const int* in_sizes, int n_in,
                              void* d_out, int out_size) {
    (void)in_sizes; (void)n_in; (void)out_size;
    const float* input  = (const float*)d_in[0];
    const void*  mask   = d_in[1];
    const int*   labels = (const int*)d_in[2];
    const float* Wh     = (const float*)d_in[3];
    const float* bh     = (const float*)d_in[4];
    const float* Wd     = (const float*)d_in[5];
    const float* bd     = (const float*)d_in[6];
    const float* Wb     = (const float*)d_in[7];
    const float* startT = (const float*)d_in[8];
    const float* trans  = (const float*)d_in[9];
    const float* endT   = (const float*)d_in[10];

    float* out     = (float*)d_out;
    float* s_out   = out + 1;
    float* dec_out = out + 1 + (size_t)Mm * Nn * Ll;

    k_pre  <<<1, 256>>>(mask, trans);
    k_mlp  <<<dim3(5, 32),        256>>>(input, Wh, bh, Wd, bd);
    k_gemmU<<<dim3(152, 32),      256>>>(Wb);
    k_gemmS<<<dim3(2, 128, 16),   256>>>(s_out);
    k_lse  <<<262144, 128>>>(s_out);
    k_num  <<<512, 256>>>(labels, trans, startT, endT);
    k_scan <<<512, 256>>>(trans, startT, endT);
    k_bt   <<<512, 256>>>(trans, endT, dec_out);
    k_loss <<<1, 256>>>(out);
}